// round 11
// baseline (speedup 1.0000x reference)
#include <cuda_runtime.h>

// ElementwiseTensorProd_o0: per token t (262144 tokens), rank R=128:
//   out[t, 0:128]   = z0l[t, :] * z0r[t, :]
//   out[t, 128:256] = sum_{m=0..2} z1l[t, m, :] * z1r[t, m, :]
//
// Traffic-minimal HBM stream (1.342 GB), measured 91.3% DRAM with float4.
// R10: Blackwell 256-bit vector loads/stores (ld/st.global.v8.f32) to halve
// LDG/STG count and L1tex wavefronts. One thread = 8 contiguous channels.

#define TOKENS 262144
#define RANK 128
#define V8_PER_ROW (RANK / 8)            // 16 float8-slots per 128-float row
#define THREADS_PER_BLOCK 512

// ---- 256-bit global load (sm_100+) ----
__device__ __forceinline__ void ldg_v8(const float* __restrict__ p, float r[8]) {
    asm volatile("ld.global.nc.v8.f32 {%0,%1,%2,%3,%4,%5,%6,%7}, [%8];"
                 : "=f"(r[0]), "=f"(r[1]), "=f"(r[2]), "=f"(r[3]),
                   "=f"(r[4]), "=f"(r[5]), "=f"(r[6]), "=f"(r[7])
                 : "l"(p));
}

// ---- 256-bit streaming global store (sm_100+) ----
__device__ __forceinline__ void stg_cs_v8(float* p, const float r[8]) {
    asm volatile("st.global.cs.v8.f32 [%0], {%1,%2,%3,%4,%5,%6,%7,%8};"
                 :: "l"(p),
                    "f"(r[0]), "f"(r[1]), "f"(r[2]), "f"(r[3]),
                    "f"(r[4]), "f"(r[5]), "f"(r[6]), "f"(r[7])
                 : "memory");
}

__global__ void __launch_bounds__(THREADS_PER_BLOCK)
etp_o0_kernel(const float* __restrict__ z0l,
              const float* __restrict__ z1l,
              const float* __restrict__ z0r,
              const float* __restrict__ z1r,
              float* __restrict__ out)
{
    // Global thread id over TOKENS * 16 float8-slots; exact grid coverage.
    const unsigned int i  = blockIdx.x * THREADS_PER_BLOCK + threadIdx.x;
    const unsigned int c8 = i & (V8_PER_ROW - 1);   // 0..15 within rank
    const unsigned int t  = i >> 4;                 // token id

    // Float-unit offsets.
    const unsigned int f0 = t * RANK + c8 * 8;              // z0 row slot
    const unsigned int f1 = t * (3 * RANK) + c8 * 8;        // z1 m=0 slot

    // ---- path (0,0,0) ----
    float a0[8], b0[8];
    ldg_v8(z0l + f0, a0);
    ldg_v8(z0r + f0, b0);

    // ---- path (1,1,0): m = 0,1,2 ----
    float a1[8], b1[8], a2[8], b2[8], a3[8], b3[8];
    ldg_v8(z1l + f1,            a1);
    ldg_v8(z1r + f1,            b1);
    ldg_v8(z1l + f1 + RANK,     a2);
    ldg_v8(z1r + f1 + RANK,     b2);
    ldg_v8(z1l + f1 + 2 * RANK, a3);
    ldg_v8(z1r + f1 + 2 * RANK, b3);

    float o00[8], o11[8];
#pragma unroll
    for (int k = 0; k < 8; k++) {
        o00[k] = a0[k] * b0[k];
        o11[k] = fmaf(a1[k], b1[k], fmaf(a2[k], b2[k], a3[k] * b3[k]));
    }

    // Output layout: (TOKENS, 2*RANK) = 256 floats per token.
    const unsigned int o = t * (2 * RANK) + c8 * 8;
    stg_cs_v8(out + o,        o00);
    stg_cs_v8(out + o + RANK, o11);
}

extern "C" void kernel_launch(void* const* d_in, const int* in_sizes, int n_in,
                              void* d_out, int out_size)
{
    (void)in_sizes; (void)n_in; (void)out_size;
    const float* z0l = (const float*)d_in[0];
    const float* z1l = (const float*)d_in[1];
    const float* z0r = (const float*)d_in[2];
    const float* z1r = (const float*)d_in[3];
    float* out = (float*)d_out;

    const unsigned int total_threads = TOKENS * V8_PER_ROW;        // 4,194,304
    const unsigned int blocks = total_threads / THREADS_PER_BLOCK; // 8192

    etp_o0_kernel<<<blocks, THREADS_PER_BLOCK>>>(z0l, z1l, z0r, z1r, out);
}

// round 12
// speedup vs baseline: 1.0072x; 1.0072x over previous
#include <cuda_runtime.h>

// ElementwiseTensorProd_o0: per token t (262144 tokens), rank R=128:
//   out[t, 0:128]   = z0l[t, :] * z0r[t, :]
//   out[t, 128:256] = sum_{m=0..2} z1l[t, m, :] * z1r[t, m, :]
//
// Traffic-minimal HBM stream (1.342 GB). Measured-best operating point
// (R4): 1 float4-slot/thread, 512-thread blocks, streaming stores.
// R11 delta: __ldcg loads (L2-only, bypass L1 — zero reuse, so skip L1
// allocation/tag work entirely).

#define TOKENS 262144
#define RANK 128
#define V4_PER_ROW (RANK / 4)            // 32 float4 per 128-float row
#define THREADS_PER_BLOCK 512

__global__ void __launch_bounds__(THREADS_PER_BLOCK)
etp_o0_kernel(const float4* __restrict__ z0l,
              const float4* __restrict__ z1l,
              const float4* __restrict__ z0r,
              const float4* __restrict__ z1r,
              float4* __restrict__ out)
{
    // Global thread id over TOKENS * 32 float4-slots; exact grid coverage.
    const unsigned int i = blockIdx.x * THREADS_PER_BLOCK + threadIdx.x;

    const unsigned int c4 = i & (V4_PER_ROW - 1);   // 0..31 within rank
    const unsigned int t  = i >> 5;                 // token id

    // ---- path (0,0,0): scalar * scalar ----
    const unsigned int i0 = t * V4_PER_ROW + c4;
    float4 a0 = __ldcg(z0l + i0);
    float4 b0 = __ldcg(z0r + i0);

    // ---- path (1,1,0): contract irrep dim m=0..2 ----
    // z1 layout: (TOKENS, 3, RANK) -> t*96 + m*32 + c4 in float4 units.
    const unsigned int i1 = t * (3 * V4_PER_ROW) + c4;
    float4 a1 = __ldcg(z1l + i1);
    float4 b1 = __ldcg(z1r + i1);
    float4 a2 = __ldcg(z1l + i1 + V4_PER_ROW);
    float4 b2 = __ldcg(z1r + i1 + V4_PER_ROW);
    float4 a3 = __ldcg(z1l + i1 + 2 * V4_PER_ROW);
    float4 b3 = __ldcg(z1r + i1 + 2 * V4_PER_ROW);

    float4 o00;
    o00.x = a0.x * b0.x;
    o00.y = a0.y * b0.y;
    o00.z = a0.z * b0.z;
    o00.w = a0.w * b0.w;

    float4 o11;
    o11.x = fmaf(a1.x, b1.x, fmaf(a2.x, b2.x, a3.x * b3.x));
    o11.y = fmaf(a1.y, b1.y, fmaf(a2.y, b2.y, a3.y * b3.y));
    o11.z = fmaf(a1.z, b1.z, fmaf(a2.z, b2.z, a3.z * b3.z));
    o11.w = fmaf(a1.w, b1.w, fmaf(a2.w, b2.w, a3.w * b3.w));

    // Output layout: (TOKENS, 2*RANK) -> 64 float4 per token.
    const unsigned int o = t * (2 * V4_PER_ROW) + c4;
    __stcs(out + o, o00);
    __stcs(out + o + V4_PER_ROW, o11);
}

extern "C" void kernel_launch(void* const* d_in, const int* in_sizes, int n_in,
                              void* d_out, int out_size)
{
    (void)in_sizes; (void)n_in; (void)out_size;
    const float4* z0l = (const float4*)d_in[0];
    const float4* z1l = (const float4*)d_in[1];
    const float4* z0r = (const float4*)d_in[2];
    const float4* z1r = (const float4*)d_in[3];
    float4* out = (float4*)d_out;

    const unsigned int total_threads = TOKENS * V4_PER_ROW;        // 8,388,608
    const unsigned int blocks = total_threads / THREADS_PER_BLOCK; // 16384

    etp_o0_kernel<<<blocks, THREADS_PER_BLOCK>>>(z0l, z1l, z0r, z1r, out);
}